// round 1
// baseline (speedup 1.0000x reference)
#include <cuda_runtime.h>
#include <cstdint>

// Problem constants
#define Bsz 16
#define Cin 128
#define Hh 64
#define Ww 64
#define Oc 256
#define KK 9           // 3x3
#define ROWLEN 1152    // Cin*KK
#define ADIM 1161      // ROWLEN + 9
#define TBL 1024
#define Rr 2.5f
#define Uu 0.83f
#define CONV_ELEMS 16777216LL  // Bsz*Oc*Hh*Ww

#define TILE_H 16
#define PATCH_ROWS 18
#define PATCH_W 66
#define Gg 4   // active channels per group in the output conv

// Device scratch (no allocs allowed)
__device__ int g_bucket[Oc];
__device__ int g_count[TBL];
__device__ int g_mask[Oc];
__device__ int g_active[Oc];
__device__ int g_nactive;

// ---------------------------------------------------------------------------
// Zero-fill output (vectorized)
// ---------------------------------------------------------------------------
__global__ void zero_out_kernel(float* __restrict__ out, int n4, int n) {
    int i = blockIdx.x * blockDim.x + threadIdx.x;
    int stride = gridDim.x * blockDim.x;
    float4 z = make_float4(0.f, 0.f, 0.f, 0.f);
    for (int j = i; j < n4; j += stride) reinterpret_cast<float4*>(out)[j] = z;
    int tail = n - n4 * 4;
    if (i < tail) out[n4 * 4 + i] = 0.f;
}

// ---------------------------------------------------------------------------
// Hash all 256 kernel rows into buckets (L2-ALSH). One block, 256 threads.
// Also zeroes the vote histogram for this call.
// ---------------------------------------------------------------------------
__global__ void hash_kernels_kernel(const float* __restrict__ kern,
                                    const float* __restrict__ a,
                                    const float* __restrict__ bptr) {
    __shared__ __align__(16) float a_s[ADIM + 3];
    __shared__ float sred[256];
    int o = threadIdx.x;
    for (int i = o; i < ADIM; i += 256) a_s[i] = a[i];
    for (int i = o; i < TBL; i += 256) g_count[i] = 0;
    __syncthreads();

    const float4* row = reinterpret_cast<const float4*>(kern + (size_t)o * ROWLEN);
    const float4* a4 = reinterpret_cast<const float4*>(a_s);
    float s = 0.f, d = 0.f;
    for (int j = 0; j < ROWLEN / 4; j++) {
        float4 kv = row[j];
        float4 av = a4[j];
        s += kv.x * kv.x + kv.y * kv.y + kv.z * kv.z + kv.w * kv.w;
        d += kv.x * av.x + kv.y * av.y + kv.z * av.z + kv.w * av.w;
    }
    sred[o] = s;
    __syncthreads();
    for (int st = 128; st > 0; st >>= 1) {
        if (o < st) sred[o] = fmaxf(sred[o], sred[o + st]);
        __syncthreads();
    }
    float smax = sred[0];
    float scale = Uu / sqrtf(smax);     // U / max row norm
    float dot = scale * d;              // scaled row . a[0:1152]
    float p = scale * scale * s;        // ||x||^2
    float acc = 0.f, t = p;
#pragma unroll
    for (int i = 0; i < 9; i++) {       // p^(2^i), i=0..8
        acc += t * a_s[ROWLEN + i];
        t = t * t;
    }
    float h = floorf((dot + acc + bptr[0]) / Rr);
    int hi = (int)h;
    int bkt = hi % TBL;
    if (bkt < 0) bkt = -bkt;
    g_bucket[o] = bkt;
}

// ---------------------------------------------------------------------------
// Vote conv: dotted = conv(input_Q, a) per pixel, bucket-vote histogram.
// Tiled: block = (ytile, batch), 256 threads, 16x64 output tile, smem patch.
// ---------------------------------------------------------------------------
__global__ void vote_kernel(const float* __restrict__ in,
                            const float* __restrict__ a,
                            const float* __restrict__ bptr) {
    __shared__ float a_s[ADIM];
    __shared__ float patch[PATCH_ROWS * PATCH_W];
    __shared__ int hist[TBL];
    int tid = threadIdx.x;
    for (int i = tid; i < ADIM; i += 256) a_s[i] = a[i];
    for (int i = tid; i < TBL; i += 256) hist[i] = 0;

    int bimg = blockIdx.y;
    int Y0 = blockIdx.x * TILE_H;
    int tx = tid & 63;
    int tyb = tid >> 6;   // 0..3, each owns 4 consecutive rows
    float acc[4] = {0.f, 0.f, 0.f, 0.f};

    const float* inb = in + (size_t)bimg * Cin * Hh * Ww;
    __syncthreads();

    for (int c = 0; c < Cin; c++) {
        __syncthreads();
        const float* ic = inb + (size_t)c * Hh * Ww;
        for (int i = tid; i < PATCH_ROWS * PATCH_W; i += 256) {
            int pr = i / PATCH_W, pc = i % PATCH_W;
            int gy = Y0 - 1 + pr, gx = pc - 1;
            float v = 0.f;
            if (gy >= 0 && gy < Hh && gx >= 0 && gx < Ww) v = ic[gy * Ww + gx];
            patch[i] = v;
        }
        __syncthreads();
        float w[9];
#pragma unroll
        for (int k = 0; k < 9; k++) w[k] = a_s[c * 9 + k];
        float r[6][3];
        int base = (tyb * 4) * PATCH_W + tx;
#pragma unroll
        for (int m = 0; m < 6; m++)
#pragma unroll
            for (int d = 0; d < 3; d++) r[m][d] = patch[base + m * PATCH_W + d];
#pragma unroll
        for (int k = 0; k < 4; k++)
#pragma unroll
            for (int dy = 0; dy < 3; dy++)
#pragma unroll
                for (int dx = 0; dx < 3; dx++)
                    acc[k] += r[k + dy][dx] * w[dy * 3 + dx];
    }

    float b0 = bptr[0];
#pragma unroll
    for (int k = 0; k < 4; k++) {
        int y = Y0 + tyb * 4 + k;
        int x = tx;
        // 0.5-filled extra channel: contributes only over in-bounds taps
        float e = 0.f;
#pragma unroll
        for (int dy = 0; dy < 3; dy++) {
            int gy = y - 1 + dy;
            if (gy < 0 || gy >= Hh) continue;
#pragma unroll
            for (int dx = 0; dx < 3; dx++) {
                int gx = x - 1 + dx;
                if (gx < 0 || gx >= Ww) continue;
                e += a_s[ROWLEN + dy * 3 + dx];
            }
        }
        float v = acc[k] + 0.5f * e;
        float h = floorf((v + b0) / Rr);
        int vi = (int)h;
        int vb = vi % TBL;
        if (vb < 0) vb = -vb;
        atomicAdd(&hist[vb], 1);
    }
    __syncthreads();
    for (int i = tid; i < TBL; i += 256) {
        int h = hist[i];
        if (h) atomicAdd(&g_count[i], h);
    }
}

// ---------------------------------------------------------------------------
// Argmax over histogram (tie -> lowest index), build mask + active list,
// write index/mask tail of the output if present.
// ---------------------------------------------------------------------------
__global__ void argmax_mask_kernel(float* __restrict__ out, long long out_size) {
    __shared__ int sval[TBL];
    __shared__ int sidx[TBL];
    int t = threadIdx.x;
    sval[t] = g_count[t];
    sidx[t] = t;
    __syncthreads();
    for (int s = TBL / 2; s > 0; s >>= 1) {
        if (t < s) {
            int v2 = sval[t + s], i2 = sidx[t + s];
            if (v2 > sval[t] || (v2 == sval[t] && i2 < sidx[t])) {
                sval[t] = v2;
                sidx[t] = i2;
            }
        }
        __syncthreads();
    }
    int winner = sidx[0];
    if (t == 0) g_nactive = 0;
    __syncthreads();
    if (t < Oc) {
        int m = (g_bucket[t] == winner) ? 1 : 0;
        g_mask[t] = m;
        if (m) {
            int pos = atomicAdd(&g_nactive, 1);
            g_active[pos] = t;
        }
        if (out_size >= CONV_ELEMS + 1 + Oc) out[CONV_ELEMS + 1 + t] = m ? 1.f : 0.f;
    }
    if (t == 0 && out_size >= CONV_ELEMS + 1) out[CONV_ELEMS] = (float)winner;
}

// ---------------------------------------------------------------------------
// Output conv over ACTIVE channels only. Blocks for inactive groups exit
// immediately; the output was pre-zeroed.
// grid = (4 ytiles, 16 batch, 64 groups of 4 channels)
// ---------------------------------------------------------------------------
__global__ void conv_active_kernel(const float* __restrict__ in,
                                   const float* __restrict__ kern,
                                   float* __restrict__ out) {
    int grp = blockIdx.z;
    int nact = g_nactive;
    if (grp * Gg >= nact) return;

    __shared__ float patch[PATCH_ROWS * PATCH_W];
    __shared__ __align__(16) float wall[Cin * Gg * 9];  // [c][g*9+k]
    int tid = threadIdx.x;

    int oc0 = (grp * Gg + 0 < nact) ? g_active[grp * Gg + 0] : -1;
    int oc1 = (grp * Gg + 1 < nact) ? g_active[grp * Gg + 1] : -1;
    int oc2 = (grp * Gg + 2 < nact) ? g_active[grp * Gg + 2] : -1;
    int oc3 = (grp * Gg + 3 < nact) ? g_active[grp * Gg + 3] : -1;
    int ocs[Gg] = {oc0, oc1, oc2, oc3};

    // stage group weights to smem (coalesced over global)
    for (int i = tid; i < Cin * Gg * 9; i += 256) {
        int c = i / (Gg * 9);
        int r = i % (Gg * 9);
        int g = r / 9, k = r % 9;
        float w = 0.f;
        int o = ocs[g];
        if (o >= 0) w = kern[(size_t)o * ROWLEN + c * 9 + k];
        wall[i] = w;
    }

    int bimg = blockIdx.y;
    int Y0 = blockIdx.x * TILE_H;
    int tx = tid & 63;
    int tyb = tid >> 6;

    float acc[4][Gg];
#pragma unroll
    for (int k = 0; k < 4; k++)
#pragma unroll
        for (int g = 0; g < Gg; g++) acc[k][g] = 0.f;

    const float* inb = in + (size_t)bimg * Cin * Hh * Ww;
    __syncthreads();

    for (int c = 0; c < Cin; c++) {
        __syncthreads();
        const float* ic = inb + (size_t)c * Hh * Ww;
        for (int i = tid; i < PATCH_ROWS * PATCH_W; i += 256) {
            int pr = i / PATCH_W, pc = i % PATCH_W;
            int gy = Y0 - 1 + pr, gx = pc - 1;
            float v = 0.f;
            if (gy >= 0 && gy < Hh && gx >= 0 && gx < Ww) v = ic[gy * Ww + gx];
            patch[i] = v;
        }
        __syncthreads();
        // weights for this c: 36 floats via 9 broadcast LDS.128
        float wf[Gg * 9];
#pragma unroll
        for (int q = 0; q < 9; q++) {
            float4 v = *reinterpret_cast<const float4*>(&wall[c * Gg * 9 + 4 * q]);
            wf[4 * q + 0] = v.x;
            wf[4 * q + 1] = v.y;
            wf[4 * q + 2] = v.z;
            wf[4 * q + 3] = v.w;
        }
        float r[6][3];
        int base = (tyb * 4) * PATCH_W + tx;
#pragma unroll
        for (int m = 0; m < 6; m++)
#pragma unroll
            for (int d = 0; d < 3; d++) r[m][d] = patch[base + m * PATCH_W + d];
#pragma unroll
        for (int k = 0; k < 4; k++)
#pragma unroll
            for (int dy = 0; dy < 3; dy++)
#pragma unroll
                for (int dx = 0; dx < 3; dx++) {
                    float v = r[k + dy][dx];
#pragma unroll
                    for (int g = 0; g < Gg; g++)
                        acc[k][g] += v * wf[g * 9 + dy * 3 + dx];
                }
    }

#pragma unroll
    for (int g = 0; g < Gg; g++) {
        int o = ocs[g];
        if (o < 0) continue;
        float* ob = out + (((size_t)bimg * Oc + o) * Hh) * Ww;
#pragma unroll
        for (int k = 0; k < 4; k++) {
            int y = Y0 + tyb * 4 + k;
            ob[y * Ww + tx] = acc[k][g];
        }
    }
}

// ---------------------------------------------------------------------------
extern "C" void kernel_launch(void* const* d_in, const int* in_sizes, int n_in,
                              void* d_out, int out_size) {
    const float* inp = (const float*)d_in[0];   // [16,128,64,64]
    const float* kern = (const float*)d_in[1];  // [256,128,3,3]
    const float* a = (const float*)d_in[2];     // [1161]
    const float* b = (const float*)d_in[3];     // [1]
    float* out = (float*)d_out;

    // 1) zero entire output (conv region + tail)
    zero_out_kernel<<<1024, 256>>>(out, out_size >> 2, out_size);
    // 2) hash kernel rows -> buckets (also zeroes histogram)
    hash_kernels_kernel<<<1, 256>>>(kern, a, b);
    // 3) vote conv + histogram
    vote_kernel<<<dim3(Hh / TILE_H, Bsz), 256>>>(inp, a, b);
    // 4) argmax -> winning bucket, mask, active list, output tail
    argmax_mask_kernel<<<1, TBL>>>(out, (long long)out_size);
    // 5) conv over active channels only (pre-zeroed elsewhere)
    conv_active_kernel<<<dim3(Hh / TILE_H, Bsz, Oc / Gg), 256>>>(inp, kern, out);
}

// round 2
// speedup vs baseline: 1.0336x; 1.0336x over previous
#include <cuda_runtime.h>
#include <cstdint>

// Problem constants
#define Bsz 16
#define Cin 128
#define Hh 64
#define Ww 64
#define HW 4096
#define Oc 256
#define KK 9           // 3x3
#define ROWLEN 1152    // Cin*KK
#define ADIM 1161      // ROWLEN + 9
#define TBL 1024
#define Rr 2.5f
#define Uu 0.83f
#define CONV_ELEMS 16777216LL  // Bsz*Oc*Hh*Ww

#define TILE_H 16
#define PATCH_ROWS 18
#define PATCH_W 66
#define NGR 8    // parallel group slots for the active conv
#define CCH 4    // channel chunks
#define CPB 32   // channels per chunk

// Device scratch (no allocs allowed)
__device__ int g_bucket[Oc];
__device__ int g_count[TBL];
__device__ int g_active[Oc];
__device__ int g_nactive;
__device__ float g_T[Bsz * KK * HW];   // 9-channel 1x1-conv intermediate (2.36 MB)

// ---------------------------------------------------------------------------
// Zero-fill output (vectorized)
// ---------------------------------------------------------------------------
__global__ void zero_out_kernel(float* __restrict__ out, int n4, int n) {
    int i = blockIdx.x * blockDim.x + threadIdx.x;
    int stride = gridDim.x * blockDim.x;
    float4 z = make_float4(0.f, 0.f, 0.f, 0.f);
    for (int j = i; j < n4; j += stride) reinterpret_cast<float4*>(out)[j] = z;
    int tail = n - n4 * 4;
    if (i < tail) out[n4 * 4 + i] = 0.f;
}

// ---------------------------------------------------------------------------
// Hash all 256 kernel rows into buckets (L2-ALSH). One block, 256 threads.
// Also zeroes the vote histogram for this call.
// ---------------------------------------------------------------------------
__global__ void hash_kernels_kernel(const float* __restrict__ kern,
                                    const float* __restrict__ a,
                                    const float* __restrict__ bptr) {
    __shared__ __align__(16) float a_s[ADIM + 3];
    __shared__ float sred[256];
    int o = threadIdx.x;
    for (int i = o; i < ADIM; i += 256) a_s[i] = a[i];
    for (int i = o; i < TBL; i += 256) g_count[i] = 0;
    __syncthreads();

    const float4* row = reinterpret_cast<const float4*>(kern + (size_t)o * ROWLEN);
    const float4* a4 = reinterpret_cast<const float4*>(a_s);
    float s = 0.f, d = 0.f;
    for (int j = 0; j < ROWLEN / 4; j++) {
        float4 kv = row[j];
        float4 av = a4[j];
        s += kv.x * kv.x + kv.y * kv.y + kv.z * kv.z + kv.w * kv.w;
        d += kv.x * av.x + kv.y * av.y + kv.z * av.z + kv.w * av.w;
    }
    sred[o] = s;
    __syncthreads();
    for (int st = 128; st > 0; st >>= 1) {
        if (o < st) sred[o] = fmaxf(sred[o], sred[o + st]);
        __syncthreads();
    }
    float smax = sred[0];
    float scale = Uu / sqrtf(smax);     // U / max row norm
    float dot = scale * d;              // scaled row . a[0:1152]
    float p = scale * scale * s;        // ||x||^2
    float acc = 0.f, t = p;
#pragma unroll
    for (int i = 0; i < 9; i++) {       // p^(2^i), i=0..8
        acc += t * a_s[ROWLEN + i];
        t = t * t;
    }
    float h = floorf((dot + acc + bptr[0]) / Rr);
    int hi = (int)h;
    int bkt = hi % TBL;
    if (bkt < 0) bkt = -bkt;
    g_bucket[o] = bkt;
}

// ---------------------------------------------------------------------------
// Vote stage A: T_k(b,p) = sum_c in(b,c,p) * a[c*9+k], k = 0..8.
// One thread per pixel; coalesced channel reduction, unrolled for MLP.
// grid = (HW/256, Bsz)
// ---------------------------------------------------------------------------
__global__ void voteA_kernel(const float* __restrict__ in,
                             const float* __restrict__ a) {
    __shared__ __align__(16) float w_s[Cin * 12];  // padded stride 12
    int tid = threadIdx.x;
    for (int i = tid; i < ROWLEN; i += 256) {
        int c = i / 9, k = i % 9;
        w_s[c * 12 + k] = a[i];
    }
    __syncthreads();

    int b = blockIdx.y;
    int p = blockIdx.x * 256 + tid;
    const float* ip = in + (size_t)b * Cin * HW + p;

    float acc[9];
#pragma unroll
    for (int k = 0; k < 9; k++) acc[k] = 0.f;

#pragma unroll 8
    for (int c = 0; c < Cin; c++) {
        float v = ip[(size_t)c * HW];
        float4 w0 = *reinterpret_cast<const float4*>(&w_s[c * 12]);
        float4 w1 = *reinterpret_cast<const float4*>(&w_s[c * 12 + 4]);
        float w8 = w_s[c * 12 + 8];
        acc[0] += v * w0.x; acc[1] += v * w0.y; acc[2] += v * w0.z; acc[3] += v * w0.w;
        acc[4] += v * w1.x; acc[5] += v * w1.y; acc[6] += v * w1.z; acc[7] += v * w1.w;
        acc[8] += v * w8;
    }
    float* tp = g_T + (size_t)b * KK * HW + p;
#pragma unroll
    for (int k = 0; k < 9; k++) tp[k * HW] = acc[k];
}

// ---------------------------------------------------------------------------
// Vote stage B: dotted(y,x) = sum_k T_k(y+dy-1,x+dx-1) + 0.5*edge; vote.
// grid = (HW/256, Bsz)
// ---------------------------------------------------------------------------
__global__ void voteB_kernel(const float* __restrict__ a,
                             const float* __restrict__ bptr) {
    __shared__ int hist[TBL];
    __shared__ float ae[9];
    int tid = threadIdx.x;
    for (int i = tid; i < TBL; i += 256) hist[i] = 0;
    if (tid < 9) ae[tid] = a[ROWLEN + tid];
    __syncthreads();

    int b = blockIdx.y;
    int p = blockIdx.x * 256 + tid;
    int y = p >> 6, x = p & 63;
    const float* tb = g_T + (size_t)b * KK * HW;

    float s = 0.f;
#pragma unroll
    for (int dy = 0; dy < 3; dy++) {
        int gy = y + dy - 1;
        if (gy < 0 || gy >= Hh) continue;
#pragma unroll
        for (int dx = 0; dx < 3; dx++) {
            int gx = x + dx - 1;
            if (gx < 0 || gx >= Ww) continue;
            int k = dy * 3 + dx;
            s += tb[k * HW + gy * Ww + gx] + 0.5f * ae[k];
        }
    }
    float h = floorf((s + bptr[0]) / Rr);
    int vi = (int)h;
    int vb = vi % TBL;
    if (vb < 0) vb = -vb;
    atomicAdd(&hist[vb], 1);
    __syncthreads();
    for (int i = tid; i < TBL; i += 256) {
        int c = hist[i];
        if (c) atomicAdd(&g_count[i], c);
    }
}

// ---------------------------------------------------------------------------
// Argmax over histogram (tie -> lowest index), build mask + active list,
// write index/mask tail of the output if present.
// ---------------------------------------------------------------------------
__global__ void argmax_mask_kernel(float* __restrict__ out, long long out_size) {
    __shared__ int sval[TBL];
    __shared__ int sidx[TBL];
    int t = threadIdx.x;
    sval[t] = g_count[t];
    sidx[t] = t;
    __syncthreads();
    for (int s = TBL / 2; s > 0; s >>= 1) {
        if (t < s) {
            int v2 = sval[t + s], i2 = sidx[t + s];
            if (v2 > sval[t] || (v2 == sval[t] && i2 < sidx[t])) {
                sval[t] = v2;
                sidx[t] = i2;
            }
        }
        __syncthreads();
    }
    int winner = sidx[0];
    if (t == 0) g_nactive = 0;
    __syncthreads();
    if (t < Oc) {
        int m = (g_bucket[t] == winner) ? 1 : 0;
        if (m) {
            int pos = atomicAdd(&g_nactive, 1);
            g_active[pos] = t;
        }
        if (out_size >= CONV_ELEMS + 1 + Oc) out[CONV_ELEMS + 1 + t] = m ? 1.f : 0.f;
    }
    if (t == 0 && out_size >= CONV_ELEMS + 1) out[CONV_ELEMS] = (float)winner;
}

// ---------------------------------------------------------------------------
// Output conv over ACTIVE channels only, channel-chunked for occupancy.
// grid = (4 ytiles, 16 batch, NGR*CCH). zg strides over active list;
// each chunk accumulates 32 channels into the pre-zeroed output via atomicAdd.
// ---------------------------------------------------------------------------
__global__ void conv_active_kernel(const float* __restrict__ in,
                                   const float* __restrict__ kern,
                                   float* __restrict__ out) {
    int nact = g_nactive;
    int zg = blockIdx.z & (NGR - 1);
    int chunk = blockIdx.z >> 3;
    if (zg >= nact) return;

    __shared__ float patch[PATCH_ROWS * PATCH_W];
    __shared__ __align__(16) float w_s[CPB * 12];  // 9 weights/channel, stride 12
    int tid = threadIdx.x;
    int tx = tid & 63;
    int tyb = tid >> 6;

    int bimg = blockIdx.y;
    int Y0 = blockIdx.x * TILE_H;
    const float* inb = in + (size_t)bimg * Cin * HW + (size_t)chunk * CPB * HW;

    for (int ai = zg; ai < nact; ai += NGR) {
        int oc = g_active[ai];
        __syncthreads();  // previous-iteration readers of w_s done
        for (int i = tid; i < CPB * 9; i += 256) {
            int c = i / 9, k = i % 9;
            w_s[c * 12 + k] = kern[(size_t)oc * ROWLEN + (chunk * CPB + c) * 9 + k];
        }

        float acc[4] = {0.f, 0.f, 0.f, 0.f};

        for (int c = 0; c < CPB; c++) {
            __syncthreads();
            const float* ic = inb + (size_t)c * HW;
            for (int i = tid; i < PATCH_ROWS * PATCH_W; i += 256) {
                int pr = i / PATCH_W, pc = i % PATCH_W;
                int gy = Y0 - 1 + pr, gx = pc - 1;
                float v = 0.f;
                if (gy >= 0 && gy < Hh && gx >= 0 && gx < Ww) v = ic[gy * Ww + gx];
                patch[i] = v;
            }
            __syncthreads();
            float4 w0 = *reinterpret_cast<const float4*>(&w_s[c * 12]);
            float4 w1 = *reinterpret_cast<const float4*>(&w_s[c * 12 + 4]);
            float w8 = w_s[c * 12 + 8];
            float w[9] = {w0.x, w0.y, w0.z, w0.w, w1.x, w1.y, w1.z, w1.w, w8};
            float r[6][3];
            int base = (tyb * 4) * PATCH_W + tx;
#pragma unroll
            for (int m = 0; m < 6; m++)
#pragma unroll
                for (int d = 0; d < 3; d++) r[m][d] = patch[base + m * PATCH_W + d];
#pragma unroll
            for (int k = 0; k < 4; k++)
#pragma unroll
                for (int dy = 0; dy < 3; dy++)
#pragma unroll
                    for (int dx = 0; dx < 3; dx++)
                        acc[k] += r[k + dy][dx] * w[dy * 3 + dx];
        }

        float* ob = out + (((size_t)bimg * Oc + oc) * Hh) * Ww;
#pragma unroll
        for (int k = 0; k < 4; k++) {
            int y = Y0 + tyb * 4 + k;
            atomicAdd(&ob[y * Ww + tx], acc[k]);
        }
    }
}

// ---------------------------------------------------------------------------
extern "C" void kernel_launch(void* const* d_in, const int* in_sizes, int n_in,
                              void* d_out, int out_size) {
    const float* inp = (const float*)d_in[0];   // [16,128,64,64]
    const float* kern = (const float*)d_in[1];  // [256,128,3,3]
    const float* a = (const float*)d_in[2];     // [1161]
    const float* b = (const float*)d_in[3];     // [1]
    float* out = (float*)d_out;

    // 1) zero entire output (conv region + tail)
    zero_out_kernel<<<2048, 256>>>(out, out_size >> 2, out_size);
    // 2) hash kernel rows -> buckets (also zeroes histogram)
    hash_kernels_kernel<<<1, 256>>>(kern, a, b);
    // 3) vote conv stage A: 9-channel 1x1 reduction
    voteA_kernel<<<dim3(HW / 256, Bsz), 256>>>(inp, a);
    // 4) vote conv stage B: shift-add + histogram
    voteB_kernel<<<dim3(HW / 256, Bsz), 256>>>(a, b);
    // 5) argmax -> winning bucket, mask, active list, output tail
    argmax_mask_kernel<<<1, TBL>>>(out, (long long)out_size);
    // 6) conv over active channels only (pre-zeroed output, chunked atomics)
    conv_active_kernel<<<dim3(Hh / TILE_H, Bsz, NGR * CCH), 256>>>(inp, kern, out);
}

// round 4
// speedup vs baseline: 3.9646x; 3.8356x over previous
#include <cuda_runtime.h>
#include <cuda_bf16.h>
#include <cstdint>

// Problem constants
#define Bsz 16
#define Cin 128
#define Hh 64
#define Ww 64
#define HW 4096
#define Oc 256
#define ROWLEN 1152
#define ADIM 1161
#define TBL 1024
#define Rr 2.5f
#define Uu 0.83f
#define CONV_ELEMS 16777216LL

// ---------------------------------------------------------------------------
// Device scratch (static, no allocs)
// ---------------------------------------------------------------------------
__device__ int g_bucket[Oc];
__device__ int g_count[TBL];
__device__ int g_active[Oc];
__device__ int g_nactive;
__device__ float g_T[Bsz * 9 * HW];                       // vote intermediate
__device__ __nv_bfloat16 g_A_hi[9 * 256 * 128];           // weights [k][m][c]
__device__ __nv_bfloat16 g_A_lo[9 * 256 * 128];
__device__ __nv_bfloat16 g_B_hi[(size_t)Bsz * HW * Cin];  // input NHWC
__device__ __nv_bfloat16 g_B_lo[(size_t)Bsz * HW * Cin];

// ---------------------------------------------------------------------------
__device__ __forceinline__ void cp_async16(uint32_t dst, const void* src, bool valid) {
    int sz = valid ? 16 : 0;
    asm volatile("cp.async.cg.shared.global [%0], [%1], 16, %2;" :: "r"(dst), "l"(src), "r"(sz) : "memory");
}
#define CP_COMMIT() asm volatile("cp.async.commit_group;" ::: "memory")
#define CP_WAIT(n) asm volatile("cp.async.wait_group %0;" :: "n"(n) : "memory")

__device__ __forceinline__ uint32_t smem_u32(const void* p) {
    uint32_t a;
    asm("{ .reg .u64 t; cvta.to.shared.u64 t, %1; cvt.u32.u64 %0, t; }" : "=r"(a) : "l"(p));
    return a;
}

#define MMA16816(d, a, b0, b1) \
    asm volatile("mma.sync.aligned.m16n8k16.row.col.f32.bf16.bf16.f32 " \
        "{%0,%1,%2,%3}, {%4,%5,%6,%7}, {%8,%9}, {%0,%1,%2,%3};" \
        : "+f"((d)[0]), "+f"((d)[1]), "+f"((d)[2]), "+f"((d)[3]) \
        : "r"((a)[0]), "r"((a)[1]), "r"((a)[2]), "r"((a)[3]), "r"(b0), "r"(b1))

// ---------------------------------------------------------------------------
__global__ void zero_out_kernel(float* __restrict__ out, int n4, int n) {
    int i = blockIdx.x * blockDim.x + threadIdx.x;
    int stride = gridDim.x * blockDim.x;
    float4 z = make_float4(0.f, 0.f, 0.f, 0.f);
    for (int j = i; j < n4; j += stride) reinterpret_cast<float4*>(out)[j] = z;
    int tail = n - n4 * 4;
    if (i < tail) out[n4 * 4 + i] = 0.f;
}

// ---------------------------------------------------------------------------
__global__ void hash_kernels_kernel(const float* __restrict__ kern,
                                    const float* __restrict__ a,
                                    const float* __restrict__ bptr) {
    __shared__ __align__(16) float a_s[ADIM + 3];
    __shared__ float sred[256];
    int o = threadIdx.x;
    for (int i = o; i < ADIM; i += 256) a_s[i] = a[i];
    for (int i = o; i < TBL; i += 256) g_count[i] = 0;
    __syncthreads();
    const float4* row = reinterpret_cast<const float4*>(kern + (size_t)o * ROWLEN);
    const float4* a4 = reinterpret_cast<const float4*>(a_s);
    float s = 0.f, d = 0.f;
    for (int j = 0; j < ROWLEN / 4; j++) {
        float4 kv = row[j], av = a4[j];
        s += kv.x * kv.x + kv.y * kv.y + kv.z * kv.z + kv.w * kv.w;
        d += kv.x * av.x + kv.y * av.y + kv.z * av.z + kv.w * av.w;
    }
    sred[o] = s;
    __syncthreads();
    for (int st = 128; st > 0; st >>= 1) {
        if (o < st) sred[o] = fmaxf(sred[o], sred[o + st]);
        __syncthreads();
    }
    float scale = Uu / sqrtf(sred[0]);
    float dot = scale * d;
    float p = scale * scale * s;
    float acc = 0.f, t = p;
#pragma unroll
    for (int i = 0; i < 9; i++) { acc += t * a_s[ROWLEN + i]; t = t * t; }
    int hi = (int)floorf((dot + acc + bptr[0]) / Rr);
    int bkt = hi % TBL;
    if (bkt < 0) bkt = -bkt;
    g_bucket[o] = bkt;
}

// ---------------------------------------------------------------------------
__global__ void voteA_kernel(const float* __restrict__ in, const float* __restrict__ a) {
    __shared__ __align__(16) float w_s[Cin * 12];
    int tid = threadIdx.x;
    for (int i = tid; i < ROWLEN; i += 256) { int c = i / 9, k = i % 9; w_s[c * 12 + k] = a[i]; }
    __syncthreads();
    int b = blockIdx.y;
    int p = blockIdx.x * 256 + tid;
    const float* ip = in + (size_t)b * Cin * HW + p;
    float acc[9];
#pragma unroll
    for (int k = 0; k < 9; k++) acc[k] = 0.f;
#pragma unroll 8
    for (int c = 0; c < Cin; c++) {
        float v = ip[(size_t)c * HW];
        float4 w0 = *reinterpret_cast<const float4*>(&w_s[c * 12]);
        float4 w1 = *reinterpret_cast<const float4*>(&w_s[c * 12 + 4]);
        float w8 = w_s[c * 12 + 8];
        acc[0] += v * w0.x; acc[1] += v * w0.y; acc[2] += v * w0.z; acc[3] += v * w0.w;
        acc[4] += v * w1.x; acc[5] += v * w1.y; acc[6] += v * w1.z; acc[7] += v * w1.w;
        acc[8] += v * w8;
    }
    float* tp = g_T + (size_t)b * 9 * HW + p;
#pragma unroll
    for (int k = 0; k < 9; k++) tp[k * HW] = acc[k];
}

__global__ void voteB_kernel(const float* __restrict__ a, const float* __restrict__ bptr) {
    __shared__ int hist[TBL];
    __shared__ float ae[9];
    int tid = threadIdx.x;
    for (int i = tid; i < TBL; i += 256) hist[i] = 0;
    if (tid < 9) ae[tid] = a[ROWLEN + tid];
    __syncthreads();
    int b = blockIdx.y;
    int p = blockIdx.x * 256 + tid;
    int y = p >> 6, x = p & 63;
    const float* tb = g_T + (size_t)b * 9 * HW;
    float s = 0.f;
#pragma unroll
    for (int dy = 0; dy < 3; dy++) {
        int gy = y + dy - 1;
        if (gy < 0 || gy >= Hh) continue;
#pragma unroll
        for (int dx = 0; dx < 3; dx++) {
            int gx = x + dx - 1;
            if (gx < 0 || gx >= Ww) continue;
            int k = dy * 3 + dx;
            s += tb[k * HW + gy * Ww + gx] + 0.5f * ae[k];
        }
    }
    int vi = (int)floorf((s + bptr[0]) / Rr);
    int vb = vi % TBL;
    if (vb < 0) vb = -vb;
    atomicAdd(&hist[vb], 1);
    __syncthreads();
    for (int i = tid; i < TBL; i += 256) {
        int c = hist[i];
        if (c) atomicAdd(&g_count[i], c);
    }
}

// ---------------------------------------------------------------------------
__global__ void argmax_mask_kernel(float* __restrict__ out, long long out_size) {
    __shared__ int sval[TBL];
    __shared__ int sidx[TBL];
    int t = threadIdx.x;
    sval[t] = g_count[t];
    sidx[t] = t;
    __syncthreads();
    for (int s = TBL / 2; s > 0; s >>= 1) {
        if (t < s) {
            int v2 = sval[t + s], i2 = sidx[t + s];
            if (v2 > sval[t] || (v2 == sval[t] && i2 < sidx[t])) { sval[t] = v2; sidx[t] = i2; }
        }
        __syncthreads();
    }
    int winner = sidx[0];
    if (t == 0) g_nactive = 0;
    __syncthreads();
    if (t < Oc) {
        int m = (g_bucket[t] == winner) ? 1 : 0;
        if (m) { int pos = atomicAdd(&g_nactive, 1); g_active[pos] = t; }
        if (out_size >= CONV_ELEMS + 1 + Oc) out[CONV_ELEMS + 1 + t] = m ? 1.f : 0.f;
    }
    if (t == 0 && out_size >= CONV_ELEMS + 1) out[CONV_ELEMS] = (float)winner;
}

// ---------------------------------------------------------------------------
// Prep A: gather active-kernel weights into [k][m][c], bf16 hi/lo split.
// ---------------------------------------------------------------------------
__global__ void prepA_kernel(const float* __restrict__ kern) {
    int idx = blockIdx.x * 256 + threadIdx.x;  // (k*256+m)*128+c
    int c = idx & 127;
    int m = (idx >> 7) & 255;
    int k = idx >> 15;
    int nact = g_nactive;
    float v = 0.f;
    if (m < nact) {
        int oc = g_active[m];
        v = kern[(size_t)oc * ROWLEN + c * 9 + k];
    }
    __nv_bfloat16 hi = __float2bfloat16_rn(v);
    __nv_bfloat16 lo = __float2bfloat16_rn(v - __bfloat162float(hi));
    g_A_hi[idx] = hi;
    g_A_lo[idx] = lo;
}

// ---------------------------------------------------------------------------
// Prep B: NCHW -> NHWC transpose with bf16 hi/lo split.
// ---------------------------------------------------------------------------
__global__ void prepB_kernel(const float* __restrict__ in) {
    __shared__ float s[128 * 33];
    int tid = threadIdx.x;
    int g = blockIdx.x * 32;
    int b = g >> 12;
    int px0 = g & 4095;
    const float* ib = in + (size_t)b * Cin * HW + px0;
    for (int i = tid; i < 32 * 128; i += 256) {
        int c = i >> 5, p = i & 31;
        s[c * 33 + p] = ib[(size_t)c * HW + p];
    }
    __syncthreads();
    for (int i = tid; i < 32 * 128; i += 256) {
        int p = i >> 7, c = i & 127;
        float v = s[c * 33 + p];
        __nv_bfloat16 hi = __float2bfloat16_rn(v);
        __nv_bfloat16 lo = __float2bfloat16_rn(v - __bfloat162float(hi));
        size_t o = (size_t)(g + p) * 128 + c;
        g_B_hi[o] = hi;
        g_B_lo[o] = lo;
    }
}

// ---------------------------------------------------------------------------
// Main conv: 9 shifted GEMMs via mma.sync bf16 3-term split.
// CTA tile: M=128 px (2 rows x 64) x N=128 ocs. K' = 9*128, chunked 18x64c.
// 8 warps: 2(M) x 4(N), warp tile 64px x 32oc.
// smem: patch hi/lo (4x66 rows x 136c pad, bf16) + 2 weight bufs + act list.
// ---------------------------------------------------------------------------
#define PSTR 136                       // patch c-stride (elems)
#define PROWB (PSTR * 2)               // 272 bytes per patch row
#define SM_PH 0
#define SM_PL 71808
#define SM_W 143616
#define WBUF 36864                     // per buffer: hi 18432 + lo 18432
#define WROWB 144                      // 72-elem padded weight row
#define SM_ACT 217344
#define SM_TOT 217856

__global__ void __launch_bounds__(256, 1)
conv_mma_kernel(float* __restrict__ out) {
    extern __shared__ char smem[];
    const int tid = threadIdx.x;
    const int lane = tid & 31;
    const int wid = tid >> 5;
    const int nact = g_nactive;
    const int n0 = blockIdx.y << 7;
    if (n0 >= nact) return;

    const int pxg = blockIdx.x << 7;     // global pixel base (b*4096 + p)
    const int bb = pxg >> 12;
    const int y0 = (pxg & 4095) >> 6;    // 2 output rows: y0, y0+1

    uint32_t sb = smem_u32(smem);

    if (tid < 128) {
        int nn = n0 + tid;
        ((int*)(smem + SM_ACT))[tid] = (nn < nact) ? g_active[nn] : -1;
    }

    // ---- patch loads: 264 rows x 16 chunks x 2 prec ----
    for (int i = tid; i < 264 * 16 * 2; i += 256) {
        int prec = (i >= 264 * 16) ? 1 : 0;
        int j = i - prec * 264 * 16;
        int row = j >> 4, ch = j & 15;
        int pr = row / 66, pc = row - pr * 66;
        int gy = y0 - 1 + pr, gx = pc - 1;
        bool v = ((unsigned)gy < 64u) && ((unsigned)gx < 64u);
        const __nv_bfloat16* base = prec ? g_B_lo : g_B_hi;
        const __nv_bfloat16* src = v ? base + (((size_t)(bb << 12) + gy * 64 + gx) * 128 + ch * 8) : base;
        uint32_t dst = sb + (prec ? SM_PL : SM_PH) + row * PROWB + ch * 16;
        cp_async16(dst, src, v);
    }
    // ---- weight chunk 0 ----
    {
        int s = 0, k = 0, chalf = 0;
        for (int i = tid; i < 2048; i += 256) {
            int prec = (i >= 1024) ? 1 : 0;
            int j = i & 1023;
            int row = j >> 3, c16 = j & 7;
            const __nv_bfloat16* base = prec ? g_A_lo : g_A_hi;
            const __nv_bfloat16* src = base + (((size_t)(k * 256 + n0 + row)) * 128 + chalf * 64 + c16 * 8);
            uint32_t dst = sb + SM_W + (s & 1) * WBUF + prec * 18432 + row * WROWB + c16 * 16;
            cp_async16(dst, src, true);
        }
        CP_COMMIT();
    }

    float d[4][4][4];
#pragma unroll
    for (int a = 0; a < 4; a++)
#pragma unroll
        for (int b2 = 0; b2 < 4; b2++)
#pragma unroll
            for (int c = 0; c < 4; c++) d[a][b2][c] = 0.f;

    const int pxbase = (wid & 1) << 6;   // 0 or 64
    const int nbase = (wid >> 1) << 5;   // 0,32,64,96

    for (int s = 0; s < 18; s++) {
        if (s < 17) {
            int s1 = s + 1;
            int k1 = s1 >> 1, ch1 = s1 & 1;
            for (int i = tid; i < 2048; i += 256) {
                int prec = (i >= 1024) ? 1 : 0;
                int j = i & 1023;
                int row = j >> 3, c16 = j & 7;
                const __nv_bfloat16* base = prec ? g_A_lo : g_A_hi;
                const __nv_bfloat16* src = base + (((size_t)(k1 * 256 + n0 + row)) * 128 + ch1 * 64 + c16 * 8);
                uint32_t dst = sb + SM_W + (s1 & 1) * WBUF + prec * 18432 + row * WROWB + c16 * 16;
                cp_async16(dst, src, true);
            }
            CP_COMMIT();
            CP_WAIT(1);
        } else {
            CP_WAIT(0);
        }
        __syncthreads();

        const int k = s >> 1, chalf = s & 1;
        const int dy = k / 3, dx = k - dy * 3;
        const int wbase = SM_W + (s & 1) * WBUF;

        int ebase[4];
#pragma unroll
        for (int mf = 0; mf < 4; mf++) {
            int px = pxbase + mf * 16 + (lane >> 2);
            ebase[mf] = (((px >> 6) + dy) * 66 + (px & 63) + dx) * PSTR;
        }
        const int coA = chalf * 64 + (lane & 3) * 2;
        const int boQ = (lane & 3) * 2;
        const int nl = lane >> 2;

#pragma unroll
        for (int cs = 0; cs < 4; cs++) {
            const int cl = cs * 16;
            uint32_t ah[4][4], al[4][4];
#pragma unroll
            for (int mf = 0; mf < 4; mf++) {
                int o = ebase[mf] + coA + cl;
                ah[mf][0] = *(const uint32_t*)(smem + SM_PH + 2 * o);
                ah[mf][1] = *(const uint32_t*)(smem + SM_PH + 2 * (o + 8 * PSTR));
                ah[mf][2] = *(const uint32_t*)(smem + SM_PH + 2 * (o + 8));
                ah[mf][3] = *(const uint32_t*)(smem + SM_PH + 2 * (o + 8 * PSTR + 8));
                al[mf][0] = *(const uint32_t*)(smem + SM_PL + 2 * o);
                al[mf][1] = *(const uint32_t*)(smem + SM_PL + 2 * (o + 8 * PSTR));
                al[mf][2] = *(const uint32_t*)(smem + SM_PL + 2 * (o + 8));
                al[mf][3] = *(const uint32_t*)(smem + SM_PL + 2 * (o + 8 * PSTR + 8));
            }
#pragma unroll
            for (int nf = 0; nf < 4; nf++) {
                int n = nbase + nf * 8 + nl;
                int bo = n * WROWB + (cl + boQ) * 2;
                uint32_t bh0 = *(const uint32_t*)(smem + wbase + bo);
                uint32_t bh1 = *(const uint32_t*)(smem + wbase + bo + 16);
                uint32_t bl0 = *(const uint32_t*)(smem + wbase + 18432 + bo);
                uint32_t bl1 = *(const uint32_t*)(smem + wbase + 18432 + bo + 16);
#pragma unroll
                for (int mf = 0; mf < 4; mf++) {
                    MMA16816(d[mf][nf], ah[mf], bh0, bh1);
                    MMA16816(d[mf][nf], ah[mf], bl0, bl1);
                    MMA16816(d[mf][nf], al[mf], bh0, bh1);
                }
            }
        }
        __syncthreads();
    }

    // ---- epilogue: scattered stores; mask n >= nact ----
    const int* act = (const int*)(smem + SM_ACT);
#pragma unroll
    for (int mf = 0; mf < 4; mf++) {
#pragma unroll
        for (int nf = 0; nf < 4; nf++) {
            int col = nbase + nf * 8 + (lane & 3) * 2;
            int oc0 = act[col];
            int oc1 = act[col + 1];
#pragma unroll
            for (int h = 0; h < 2; h++) {
                int row = pxbase + mf * 16 + (lane >> 2) + h * 8;
                int y = y0 + (row >> 6);
                int x = row & 63;
                size_t pixoff = (size_t)y * 64 + x;
                if (oc0 >= 0)
                    out[(((size_t)bb * Oc + oc0) << 12) + pixoff] = d[mf][nf][h * 2 + 0];
                if (oc1 >= 0)
                    out[(((size_t)bb * Oc + oc1) << 12) + pixoff] = d[mf][nf][h * 2 + 1];
            }
        }
    }
}

// ---------------------------------------------------------------------------
extern "C" void kernel_launch(void* const* d_in, const int* in_sizes, int n_in,
                              void* d_out, int out_size) {
    const float* inp = (const float*)d_in[0];
    const float* kern = (const float*)d_in[1];
    const float* a = (const float*)d_in[2];
    const float* b = (const float*)d_in[3];
    float* out = (float*)d_out;

    static int attr_set = 0;
    cudaFuncSetAttribute(conv_mma_kernel, cudaFuncAttributeMaxDynamicSharedMemorySize, SM_TOT);
    (void)attr_set;

    zero_out_kernel<<<2048, 256>>>(out, out_size >> 2, out_size);
    hash_kernels_kernel<<<1, 256>>>(kern, a, b);
    voteA_kernel<<<dim3(HW / 256, Bsz), 256>>>(inp, a);
    voteB_kernel<<<dim3(HW / 256, Bsz), 256>>>(a, b);
    argmax_mask_kernel<<<1, TBL>>>(out, (long long)out_size);
    prepA_kernel<<<1152, 256>>>(kern);
    prepB_kernel<<<2048, 256>>>(inp);
    conv_mma_kernel<<<dim3(512, 2), 256, SM_TOT>>>(out);
}